// round 1
// baseline (speedup 1.0000x reference)
#include <cuda_runtime.h>
#include <math.h>

// Problem constants
#define BB 4
#define TT 2048
#define DD 1024
#define HH 4
#define KDIM 256
#define VDIM 256
#define MM 64
#define BT (BB*TT)            // 8192
#define NQK (HH*KDIM)         // 1024
#define KCH 8                 // k-chunks in pass A (32 k each)
#define VCH 8                 // v-chunks in pass B (32 v each)

// Scratch (static device allocations; no cudaMalloc allowed)
__device__ float g_q [BB*HH*TT*KDIM];           // swish(xWq)*scale, [b,h,t,k]
__device__ float g_k [BB*HH*TT*KDIM];           // swish(xWk),       [b,h,t,k]
__device__ float g_v [BB*HH*TT*VDIM];           // xWv,              [b,h,t,v]
__device__ float g_ge[BB*HH*TT*MM];             // exp(f),           [b,h,t,m]
__device__ float g_part[BB*HH*TT*KCH*MM];       // partial logits [b,h,t,chunk,m]
__device__ float g_p [BB*HH*TT*MM];             // softmax probs  [b,h,t,m]
__device__ float g_o [BB*HH*TT*VDIM];           // pre-norm output [b,h,t,v]
__device__ float g_on[(size_t)BT*DD];           // normalized, [b,t, h*V+v]

// ---------------------------------------------------------------------------
// Kernel 1: fused projection GEMM. x(8192x1024) @ [Wq|Wk|Wv|Wf] with fused
// activations in the epilogue. 128x128x8 fp32 tiles, 256 threads, 8x8 micro.
// ---------------------------------------------------------------------------
__global__ __launch_bounds__(256) void proj_gemm(
    const float* __restrict__ X,
    const float* __restrict__ Wq, const float* __restrict__ Wk,
    const float* __restrict__ Wv, const float* __restrict__ Wf) {
  __shared__ float As[8][128];
  __shared__ float Bs[8][128];

  int nt = blockIdx.x;   // 0..25 column tile
  int by = blockIdx.y;   // 0..63 row tile
  const float* Wb; int ldb, seg, ncol0;
  if (nt < 8)       { Wb = Wq; ldb = NQK;   seg = 0; ncol0 = nt      * 128; }
  else if (nt < 16) { Wb = Wk; ldb = NQK;   seg = 1; ncol0 = (nt-8)  * 128; }
  else if (nt < 24) { Wb = Wv; ldb = NQK;   seg = 2; ncol0 = (nt-16) * 128; }
  else              { Wb = Wf; ldb = HH*MM; seg = 3; ncol0 = (nt-24) * 128; }

  int tid = threadIdx.x;
  int a_row = tid >> 1, a_col = (tid & 1) * 4;   // A: 128 rows x 8 k
  int b_row = tid >> 5, b_col = (tid & 31) * 4;  // B: 8 rows  x 128 n
  const float* Ap = X  + (size_t)(by*128 + a_row)*DD + a_col;
  const float* Bp = Wb + (size_t)b_row*ldb + ncol0 + b_col;

  float acc[8][8];
  #pragma unroll
  for (int i = 0; i < 8; i++)
    #pragma unroll
    for (int j = 0; j < 8; j++) acc[i][j] = 0.0f;

  int trow = (tid >> 4) * 8;
  int tcol = (tid & 15) * 8;

  for (int k0 = 0; k0 < DD; k0 += 8) {
    float4 av = *(const float4*)(Ap + k0);
    As[a_col+0][a_row] = av.x;
    As[a_col+1][a_row] = av.y;
    As[a_col+2][a_row] = av.z;
    As[a_col+3][a_row] = av.w;
    *(float4*)&Bs[b_row][b_col] = *(const float4*)(Bp + (size_t)k0*ldb);
    __syncthreads();
    #pragma unroll
    for (int kk = 0; kk < 8; kk++) {
      float ar[8], br[8];
      *(float4*)&ar[0] = *(float4*)&As[kk][trow];
      *(float4*)&ar[4] = *(float4*)&As[kk][trow+4];
      *(float4*)&br[0] = *(float4*)&Bs[kk][tcol];
      *(float4*)&br[4] = *(float4*)&Bs[kk][tcol+4];
      #pragma unroll
      for (int i = 0; i < 8; i++)
        #pragma unroll
        for (int j = 0; j < 8; j++) acc[i][j] += ar[i] * br[j];
    }
    __syncthreads();
  }

  // epilogue with fused activations + layout transpose to [b,h,t,*]
  #pragma unroll
  for (int i = 0; i < 8; i++) {
    int gm = by*128 + trow + i;          // b*T + t
    int b = gm >> 11, t = gm & (TT-1);
    #pragma unroll
    for (int j = 0; j < 8; j++) {
      int gn = ncol0 + tcol + j;         // column within this weight matrix
      float u = acc[i][j];
      if (seg <= 1) {
        float sw = u / (1.0f + expf(-u));          // swish
        if (seg == 0) sw *= 0.0625f;               // fold K^-0.5 into q
        int h = gn >> 8, c = gn & 255;
        float* dst = (seg == 0) ? g_q : g_k;
        dst[((size_t)((b*HH + h)*TT + t))*KDIM + c] = sw;
      } else if (seg == 2) {
        int h = gn >> 8, c = gn & 255;
        g_v[((size_t)((b*HH + h)*TT + t))*VDIM + c] = u;
      } else {
        // f = log_sigmoid(u)/8 ; ge = exp(f)
        float ls = fminf(u, 0.0f) - log1pf(expf(-fabsf(u)));
        float ge = expf(0.125f * ls);
        int h = gn >> 6, c = gn & 63;
        g_ge[((size_t)((b*HH + h)*TT + t))*MM + c] = ge;
      }
    }
  }
}

// ---------------------------------------------------------------------------
// Kernel 2: pass A — hk recurrence + partial logits per k-chunk.
// grid (KCH, H, B), 64 threads (thread = slot m). Each thread holds a 32-k
// slice of hk[:,m] in 8 float4 registers.
// ---------------------------------------------------------------------------
__global__ __launch_bounds__(64) void passA_kernel(void) {
  int chunk = blockIdx.x;                  // 32 k's per chunk
  int h = blockIdx.y, b = blockIdx.z;
  int m = threadIdx.x;                     // 0..63
  size_t row0 = (size_t)(b*HH + h) * TT;

  const float* kp  = g_k  + row0*KDIM + chunk*32;
  const float* qp  = g_q  + row0*KDIM + chunk*32;
  const float* gep = g_ge + row0*MM   + m;
  float*       pp  = g_part + ((size_t)row0*KCH + chunk)*MM + m;

  __shared__ float4 skq[16];   // [0..7]=k chunk, [8..15]=q chunk

  float4 hk[8];
  #pragma unroll
  for (int i = 0; i < 8; i++) hk[i] = make_float4(0.f,0.f,0.f,0.f);

  float kq_n = (m < 32) ? kp[m] : qp[m - 32];
  float ge_n = gep[0];

  for (int t = 0; t < TT; t++) {
    ((float*)skq)[m] = kq_n;
    __syncthreads();
    float ge = ge_n;
    float s  = 1.0f - ge;
    if (t + 1 < TT) {
      kq_n = (m < 32) ? kp[(size_t)(t+1)*KDIM + m] : qp[(size_t)(t+1)*KDIM + m - 32];
      ge_n = gep[(size_t)(t+1)*MM];
    }
    float4 a0 = make_float4(0.f,0.f,0.f,0.f);
    #pragma unroll
    for (int i = 0; i < 8; i++) {
      float4 kv = skq[i];
      float4 qv = skq[8+i];
      hk[i].x = hk[i].x*ge + kv.x*s;  a0.x += qv.x*hk[i].x;
      hk[i].y = hk[i].y*ge + kv.y*s;  a0.y += qv.y*hk[i].y;
      hk[i].z = hk[i].z*ge + kv.z*s;  a0.z += qv.z*hk[i].z;
      hk[i].w = hk[i].w*ge + kv.w*s;  a0.w += qv.w*hk[i].w;
    }
    pp[(size_t)t * (KCH*MM)] = (a0.x + a0.y) + (a0.z + a0.w);
    __syncthreads();
  }
}

// ---------------------------------------------------------------------------
// Kernel 3: reduce partials over k-chunks + softmax over M=64.
// One warp per (b,h,t) row.
// ---------------------------------------------------------------------------
__global__ __launch_bounds__(256) void softmax_kernel(void) {
  int warp = threadIdx.x >> 5, lane = threadIdx.x & 31;
  size_t row = (size_t)blockIdx.x * 8 + warp;   // 0..32767
  const float* pp = g_part + row * (KCH*MM);
  float l0 = 0.f, l1 = 0.f;
  #pragma unroll
  for (int c = 0; c < KCH; c++) {
    l0 += pp[c*MM + lane];
    l1 += pp[c*MM + lane + 32];
  }
  float mx = fmaxf(l0, l1);
  #pragma unroll
  for (int o = 16; o > 0; o >>= 1) mx = fmaxf(mx, __shfl_xor_sync(0xffffffffu, mx, o));
  float e0 = __expf(l0 - mx), e1 = __expf(l1 - mx);
  float sum = e0 + e1;
  #pragma unroll
  for (int o = 16; o > 0; o >>= 1) sum += __shfl_xor_sync(0xffffffffu, sum, o);
  float inv = 1.0f / sum;
  g_p[row*MM + lane]      = e0 * inv;
  g_p[row*MM + lane + 32] = e1 * inv;
}

// ---------------------------------------------------------------------------
// Kernel 4: pass B — hv recurrence + output, per v-chunk.
// grid (VCH, H, B), 128 threads: v = tid&31 (32 v per CTA), mg = tid>>5
// (4 m-groups of 16). Each thread holds hv[16] (its 16 m's for its v).
// ---------------------------------------------------------------------------
__global__ __launch_bounds__(128) void passB_kernel(void) {
  int vch = blockIdx.x;
  int h = blockIdx.y, b = blockIdx.z;
  int tid = threadIdx.x;
  int v  = tid & 31;
  int mg = tid >> 5;                       // 0..3
  size_t row0 = (size_t)(b*HH + h) * TT;

  const float* vp = g_v  + row0*VDIM + vch*32 + v;
  const float* pp = g_p  + row0*MM;
  const float* gp = g_ge + row0*MM;
  float*       op = g_o  + row0*VDIM + vch*32 + v;

  __shared__ float sp[MM];
  __shared__ float sge[MM];
  __shared__ float red[3][32];

  float hv[16];
  #pragma unroll
  for (int i = 0; i < 16; i++) hv[i] = 0.0f;

  float pg_n = (tid < 64) ? pp[tid] : gp[tid - 64];
  float vt_n = vp[0];

  for (int t = 0; t < TT; t++) {
    if (tid < 64) sp[tid] = pg_n; else sge[tid - 64] = pg_n;
    __syncthreads();
    float vt = vt_n;
    if (t + 1 < TT) {
      pg_n = (tid < 64) ? pp[(size_t)(t+1)*MM + tid] : gp[(size_t)(t+1)*MM + tid - 64];
      vt_n = vp[(size_t)(t+1)*VDIM];
    }
    float4 o4 = make_float4(0.f,0.f,0.f,0.f);
    #pragma unroll
    for (int i = 0; i < 4; i++) {
      float4 ge4 = *(float4*)&sge[mg*16 + i*4];
      float4 p4  = *(float4*)&sp [mg*16 + i*4];
      int bi = i*4;
      // hv = ge*hv + (1-ge)*vt  ==  (hv - vt)*ge + vt
      hv[bi+0] = (hv[bi+0]-vt)*ge4.x + vt;  o4.x += p4.x*hv[bi+0];
      hv[bi+1] = (hv[bi+1]-vt)*ge4.y + vt;  o4.y += p4.y*hv[bi+1];
      hv[bi+2] = (hv[bi+2]-vt)*ge4.z + vt;  o4.z += p4.z*hv[bi+2];
      hv[bi+3] = (hv[bi+3]-vt)*ge4.w + vt;  o4.w += p4.w*hv[bi+3];
    }
    float osum = (o4.x + o4.y) + (o4.z + o4.w);
    if (mg) red[mg-1][v] = osum;
    __syncthreads();
    if (mg == 0)
      op[(size_t)t*VDIM] = osum + red[0][v] + red[1][v] + red[2][v];
  }
}

// ---------------------------------------------------------------------------
// Kernel 5: per-head RMSNorm + layout change to [b,t, h*V+v].
// One warp per (b,h,t) row of 256.
// ---------------------------------------------------------------------------
__global__ __launch_bounds__(256) void norm_kernel(const float* __restrict__ gw) {
  int warp = threadIdx.x >> 5, lane = threadIdx.x & 31;
  size_t row = (size_t)blockIdx.x * 8 + warp;    // (b*H+h)*T + t
  const float* orow = g_o + row * VDIM;
  float4 x0 = *(const float4*)(orow + lane*8);
  float4 x1 = *(const float4*)(orow + lane*8 + 4);
  float ss = x0.x*x0.x + x0.y*x0.y + x0.z*x0.z + x0.w*x0.w
           + x1.x*x1.x + x1.y*x1.y + x1.z*x1.z + x1.w*x1.w;
  #pragma unroll
  for (int o = 16; o > 0; o >>= 1) ss += __shfl_xor_sync(0xffffffffu, ss, o);
  float rstd = rsqrtf(ss * (1.0f/VDIM) + 1e-5f);
  int t = row & (TT-1); int bh = (int)(row >> 11); int b = bh >> 2, h = bh & 3;
  float* drow = g_on + ((size_t)(b*TT + t))*DD + h*VDIM + lane*8;
  float4 w0 = *(const float4*)(gw + lane*8);
  float4 w1 = *(const float4*)(gw + lane*8 + 4);
  float4 y0, y1;
  y0.x = x0.x*rstd*w0.x; y0.y = x0.y*rstd*w0.y; y0.z = x0.z*rstd*w0.z; y0.w = x0.w*rstd*w0.w;
  y1.x = x1.x*rstd*w1.x; y1.y = x1.y*rstd*w1.y; y1.z = x1.z*rstd*w1.z; y1.w = x1.w*rstd*w1.w;
  *(float4*)(drow)     = y0;
  *(float4*)(drow + 4) = y1;
}

// ---------------------------------------------------------------------------
// Kernel 6: output GEMM. g_on(8192x1024) @ Wo(1024x1024) -> d_out.
// ---------------------------------------------------------------------------
__global__ __launch_bounds__(256) void out_gemm(
    const float* __restrict__ Wo, float* __restrict__ C) {
  __shared__ float As[8][128];
  __shared__ float Bs[8][128];
  int bx = blockIdx.x;    // 0..7
  int by = blockIdx.y;    // 0..63
  int tid = threadIdx.x;
  int a_row = tid >> 1, a_col = (tid & 1) * 4;
  int b_row = tid >> 5, b_col = (tid & 31) * 4;
  const float* Ap = g_on + (size_t)(by*128 + a_row)*DD + a_col;
  const float* Bp = Wo   + (size_t)b_row*DD + bx*128 + b_col;

  float acc[8][8];
  #pragma unroll
  for (int i = 0; i < 8; i++)
    #pragma unroll
    for (int j = 0; j < 8; j++) acc[i][j] = 0.0f;

  int trow = (tid >> 4) * 8;
  int tcol = (tid & 15) * 8;

  for (int k0 = 0; k0 < DD; k0 += 8) {
    float4 av = *(const float4*)(Ap + k0);
    As[a_col+0][a_row] = av.x;
    As[a_col+1][a_row] = av.y;
    As[a_col+2][a_row] = av.z;
    As[a_col+3][a_row] = av.w;
    *(float4*)&Bs[b_row][b_col] = *(const float4*)(Bp + (size_t)k0*DD);
    __syncthreads();
    #pragma unroll
    for (int kk = 0; kk < 8; kk++) {
      float ar[8], br[8];
      *(float4*)&ar[0] = *(float4*)&As[kk][trow];
      *(float4*)&ar[4] = *(float4*)&As[kk][trow+4];
      *(float4*)&br[0] = *(float4*)&Bs[kk][tcol];
      *(float4*)&br[4] = *(float4*)&Bs[kk][tcol+4];
      #pragma unroll
      for (int i = 0; i < 8; i++)
        #pragma unroll
        for (int j = 0; j < 8; j++) acc[i][j] += ar[i] * br[j];
    }
    __syncthreads();
  }

  #pragma unroll
  for (int i = 0; i < 8; i++) {
    size_t gm = (size_t)by*128 + trow + i;
    float* crow = C + gm*DD + bx*128 + tcol;
    *(float4*)(crow)     = make_float4(acc[i][0], acc[i][1], acc[i][2], acc[i][3]);
    *(float4*)(crow + 4) = make_float4(acc[i][4], acc[i][5], acc[i][6], acc[i][7]);
  }
}

// ---------------------------------------------------------------------------
extern "C" void kernel_launch(void* const* d_in, const int* in_sizes, int n_in,
                              void* d_out, int out_size) {
  const float* x   = (const float*)d_in[0];
  const float* Wq  = (const float*)d_in[1];
  const float* Wk  = (const float*)d_in[2];
  const float* Wv  = (const float*)d_in[3];
  const float* Wf  = (const float*)d_in[4];
  const float* gw  = (const float*)d_in[5];
  const float* Wo  = (const float*)d_in[6];
  float* out = (float*)d_out;

  proj_gemm<<<dim3(26, 64), 256>>>(x, Wq, Wk, Wv, Wf);
  passA_kernel<<<dim3(KCH, HH, BB), 64>>>();
  softmax_kernel<<<4096, 256>>>();
  passB_kernel<<<dim3(VCH, HH, BB), 128>>>();
  norm_kernel<<<4096, 256>>>(gw);
  out_gemm<<<dim3(8, 64), 256>>>(Wo, out);
}

// round 3
// speedup vs baseline: 1.3384x; 1.3384x over previous
#include <cuda_runtime.h>
#include <math.h>
#include <stdint.h>

// Problem constants
#define BB 4
#define TT 2048
#define DD 1024
#define HH 4
#define KDIM 256
#define VDIM 256
#define MM 64
#define BT (BB*TT)            // 8192
#define NQK (HH*KDIM)         // 1024
#define KCH 16                // k-chunks in pass A (16 k each)
#define VCH 8                 // v-chunks in pass B (32 v each)

#define LDA_S 20              // smem A row stride (floats), tile 128 x 16
#define LDB_S 136             // smem B row stride (floats), tile 16 x 128

// Scratch (static device allocations; no cudaMalloc allowed)
__device__ float g_x32[(size_t)BT*DD];          // tf32-rounded x
__device__ float g_wq32[DD*NQK];
__device__ float g_wk32[DD*NQK];
__device__ float g_wv32[DD*NQK];
__device__ float g_wf32[DD*HH*MM];
__device__ float g_wo32[DD*DD];
__device__ float g_q [BB*HH*TT*KDIM];           // swish(xWq)*scale, [b,h,t,k]
__device__ float g_k [BB*HH*TT*KDIM];           // swish(xWk),       [b,h,t,k]
__device__ float g_v [BB*HH*TT*VDIM];           // xWv,              [b,h,t,v]
__device__ float g_ge[BB*HH*TT*MM];             // exp(f),           [b,h,t,m]
__device__ float g_part[(size_t)BB*HH*TT*KCH*MM]; // partial logits
__device__ float g_p [BB*HH*TT*MM];             // softmax probs  [b,h,t,m]
__device__ float g_o [BB*HH*TT*VDIM];           // pre-norm output [b,h,t,v]
__device__ float g_on[(size_t)BT*DD];           // normalized (tf32-rounded)

// ---------------------------------------------------------------------------
// tf32 helpers
// ---------------------------------------------------------------------------
__device__ __forceinline__ float cvt_rna_tf32(float x) {
  uint32_t r;
  asm("cvt.rna.tf32.f32 %0, %1;" : "=r"(r) : "f"(x));   // tf32 dest is .b32
  return __uint_as_float(r);
}

__device__ __forceinline__ void mma_tf32(float* c, const uint32_t* a, const uint32_t* b) {
  asm volatile(
      "mma.sync.aligned.m16n8k8.row.col.f32.tf32.tf32.f32 "
      "{%0,%1,%2,%3}, {%4,%5,%6,%7}, {%8,%9}, {%0,%1,%2,%3};"
      : "+f"(c[0]), "+f"(c[1]), "+f"(c[2]), "+f"(c[3])
      : "r"(a[0]), "r"(a[1]), "r"(a[2]), "r"(a[3]), "r"(b[0]), "r"(b[1]));
}

__device__ __forceinline__ void cpa16(void* smem, const void* g) {
  uint32_t s = (uint32_t)__cvta_generic_to_shared(smem);
  asm volatile("cp.async.cg.shared.global [%0], [%1], 16;" :: "r"(s), "l"(g));
}
__device__ __forceinline__ void cp_commit() { asm volatile("cp.async.commit_group;"); }
__device__ __forceinline__ void cp_wait1() { asm volatile("cp.async.wait_group 1;"); }
__device__ __forceinline__ void cp_wait0() { asm volatile("cp.async.wait_group 0;"); }

// ---------------------------------------------------------------------------
// Kernel 0: round fp32 -> tf32 (rna) elementwise, float4-wide.
// ---------------------------------------------------------------------------
__global__ __launch_bounds__(256) void cvt_tf32_kernel(
    const float* __restrict__ src, float* __restrict__ dst, int n4) {
  int i = blockIdx.x * 256 + threadIdx.x;
  if (i < n4) {
    float4 v = ((const float4*)src)[i];
    v.x = cvt_rna_tf32(v.x); v.y = cvt_rna_tf32(v.y);
    v.z = cvt_rna_tf32(v.z); v.w = cvt_rna_tf32(v.w);
    ((float4*)dst)[i] = v;
  }
}

// ---------------------------------------------------------------------------
// Shared GEMM machinery: CTA 128x128, 8 warps (2x4), warp 64x32, k-slab 16.
// ---------------------------------------------------------------------------
__device__ __forceinline__ void gemm_load_stage(
    float* sA, float* sB, const float* Ag, const float* Bg, int ldb, int k0, int tid) {
  int ac = tid * 2;
  {
    int r = ac >> 2, s = (ac & 3) * 4;
    cpa16(&sA[r * LDA_S + s], Ag + (size_t)r * DD + k0 + s);
  }
  {
    int r = (ac + 1) >> 2, s = ((ac + 1) & 3) * 4;
    cpa16(&sA[r * LDA_S + s], Ag + (size_t)r * DD + k0 + s);
  }
  int bc = tid * 2;
  {
    int r = bc >> 5, s = (bc & 31) * 4;
    cpa16(&sB[r * LDB_S + s], Bg + (size_t)(k0 + r) * ldb + s);
  }
  {
    int r = (bc + 1) >> 5, s = ((bc + 1) & 31) * 4;
    cpa16(&sB[r * LDB_S + s], Bg + (size_t)(k0 + r) * ldb + s);
  }
}

__device__ __forceinline__ void gemm_compute16(
    const float* sA, const float* sB, float acc[4][4][4],
    int grp, int kq, int wm0, int wn0) {
  #pragma unroll
  for (int kb = 0; kb < 16; kb += 8) {
    uint32_t a[4][4], b[4][2];
    #pragma unroll
    for (int mi = 0; mi < 4; mi++) {
      const uint32_t* ap = (const uint32_t*)(sA + (wm0 + 16 * mi + grp) * LDA_S + kb + kq);
      a[mi][0] = ap[0];
      a[mi][1] = ap[8 * LDA_S];
      a[mi][2] = ap[4];
      a[mi][3] = ap[8 * LDA_S + 4];
    }
    #pragma unroll
    for (int ni = 0; ni < 4; ni++) {
      const uint32_t* bp = (const uint32_t*)(sB + (kb + kq) * LDB_S + wn0 + 8 * ni + grp);
      b[ni][0] = bp[0];
      b[ni][1] = bp[4 * LDB_S];
    }
    #pragma unroll
    for (int mi = 0; mi < 4; mi++)
      #pragma unroll
      for (int ni = 0; ni < 4; ni++)
        mma_tf32(acc[mi][ni], a[mi], b[ni]);
  }
}

// ---------------------------------------------------------------------------
// Kernel 1: fused projection GEMM (tf32 tensor cores) + activation epilogue.
// ---------------------------------------------------------------------------
__global__ __launch_bounds__(256) void proj_gemm_tc(void) {
  __shared__ __align__(16) float sA[2][128 * LDA_S];
  __shared__ __align__(16) float sB[2][16 * LDB_S];

  int nt = blockIdx.x;
  const float* Wb; int ldb, seg, ncol0;
  if (nt < 8)       { Wb = g_wq32; ldb = NQK;   seg = 0; ncol0 = nt       * 128; }
  else if (nt < 16) { Wb = g_wk32; ldb = NQK;   seg = 1; ncol0 = (nt - 8) * 128; }
  else if (nt < 24) { Wb = g_wv32; ldb = NQK;   seg = 2; ncol0 = (nt - 16) * 128; }
  else              { Wb = g_wf32; ldb = HH*MM; seg = 3; ncol0 = (nt - 24) * 128; }

  int tid = threadIdx.x;
  int lane = tid & 31, warp = tid >> 5;
  int grp = lane >> 2, kq = lane & 3;
  int wm0 = (warp >> 2) * 64, wn0 = (warp & 3) * 32;

  const float* Ag = g_x32 + (size_t)(blockIdx.y * 128) * DD;
  const float* Bg = Wb + ncol0;

  float acc[4][4][4];
  #pragma unroll
  for (int i = 0; i < 4; i++)
    #pragma unroll
    for (int j = 0; j < 4; j++)
      #pragma unroll
      for (int r = 0; r < 4; r++) acc[i][j][r] = 0.0f;

  gemm_load_stage(sA[0], sB[0], Ag, Bg, ldb, 0, tid);
  cp_commit();

  for (int s = 0; s < 64; s++) {
    if (s < 63) {
      gemm_load_stage(sA[(s + 1) & 1], sB[(s + 1) & 1], Ag, Bg, ldb, (s + 1) * 16, tid);
      cp_commit();
      cp_wait1();
    } else {
      cp_wait0();
    }
    __syncthreads();
    gemm_compute16(sA[s & 1], sB[s & 1], acc, grp, kq, wm0, wn0);
    __syncthreads();
  }

  #pragma unroll
  for (int mi = 0; mi < 4; mi++) {
    #pragma unroll
    for (int rh = 0; rh < 2; rh++) {
      int gm = blockIdx.y * 128 + wm0 + 16 * mi + grp + 8 * rh;   // b*T + t
      int b = gm >> 11, t = gm & (TT - 1);
      #pragma unroll
      for (int ni = 0; ni < 4; ni++) {
        #pragma unroll
        for (int cc = 0; cc < 2; cc++) {
          float u = acc[mi][ni][rh * 2 + cc];
          int gn = ncol0 + wn0 + 8 * ni + 2 * kq + cc;
          if (seg <= 1) {
            float sw = u / (1.0f + expf(-u));          // swish
            if (seg == 0) sw *= 0.0625f;               // fold K^-0.5 into q
            int h = gn >> 8, c = gn & 255;
            float* dst = (seg == 0) ? g_q : g_k;
            dst[((size_t)((b * HH + h) * TT + t)) * KDIM + c] = sw;
          } else if (seg == 2) {
            int h = gn >> 8, c = gn & 255;
            g_v[((size_t)((b * HH + h) * TT + t)) * VDIM + c] = u;
          } else {
            float ls = fminf(u, 0.0f) - log1pf(expf(-fabsf(u)));
            float ge = expf(0.125f * ls);
            int h = gn >> 6, c = gn & 63;
            g_ge[((size_t)((b * HH + h) * TT + t)) * MM + c] = ge;
          }
        }
      }
    }
  }
}

// ---------------------------------------------------------------------------
// Kernel 2: pass A — hk recurrence + partial logits per k-chunk (16 k/CTA).
// ---------------------------------------------------------------------------
__global__ __launch_bounds__(64) void passA_kernel(void) {
  int chunk = blockIdx.x;
  int h = blockIdx.y, b = blockIdx.z;
  int m = threadIdx.x;
  size_t row0 = (size_t)(b * HH + h) * TT;

  const float* kp  = g_k  + row0 * KDIM + chunk * 16;
  const float* qp  = g_q  + row0 * KDIM + chunk * 16;
  const float* gep = g_ge + row0 * MM + m;
  float*       pp  = g_part + ((size_t)row0 * KCH + chunk) * MM + m;

  __shared__ float4 skq[8];

  float4 hk[4];
  #pragma unroll
  for (int i = 0; i < 4; i++) hk[i] = make_float4(0.f, 0.f, 0.f, 0.f);

  float kq_n = 0.0f;
  if (m < 16) kq_n = kp[m];
  else if (m < 32) kq_n = qp[m - 16];
  float ge_n = gep[0];

  for (int t = 0; t < TT; t++) {
    if (m < 32) ((float*)skq)[m] = kq_n;
    __syncthreads();
    float ge = ge_n;
    float s = 1.0f - ge;
    if (t + 1 < TT) {
      if (m < 16)      kq_n = kp[(size_t)(t + 1) * KDIM + m];
      else if (m < 32) kq_n = qp[(size_t)(t + 1) * KDIM + m - 16];
      ge_n = gep[(size_t)(t + 1) * MM];
    }
    float4 a0 = make_float4(0.f, 0.f, 0.f, 0.f);
    #pragma unroll
    for (int i = 0; i < 4; i++) {
      float4 kv = skq[i];
      float4 qv = skq[4 + i];
      hk[i].x = hk[i].x * ge + kv.x * s;  a0.x += qv.x * hk[i].x;
      hk[i].y = hk[i].y * ge + kv.y * s;  a0.y += qv.y * hk[i].y;
      hk[i].z = hk[i].z * ge + kv.z * s;  a0.z += qv.z * hk[i].z;
      hk[i].w = hk[i].w * ge + kv.w * s;  a0.w += qv.w * hk[i].w;
    }
    pp[(size_t)t * (KCH * MM)] = (a0.x + a0.y) + (a0.z + a0.w);
    __syncthreads();
  }
}

// ---------------------------------------------------------------------------
// Kernel 3: reduce partials + softmax over M=64. One warp per (b,h,t).
// ---------------------------------------------------------------------------
__global__ __launch_bounds__(256) void softmax_kernel(void) {
  int warp = threadIdx.x >> 5, lane = threadIdx.x & 31;
  size_t row = (size_t)blockIdx.x * 8 + warp;
  const float* pp = g_part + row * (KCH * MM);
  float l0 = 0.f, l1 = 0.f;
  #pragma unroll
  for (int c = 0; c < KCH; c++) {
    l0 += pp[c * MM + lane];
    l1 += pp[c * MM + lane + 32];
  }
  float mx = fmaxf(l0, l1);
  #pragma unroll
  for (int o = 16; o > 0; o >>= 1) mx = fmaxf(mx, __shfl_xor_sync(0xffffffffu, mx, o));
  float e0 = __expf(l0 - mx), e1 = __expf(l1 - mx);
  float sum = e0 + e1;
  #pragma unroll
  for (int o = 16; o > 0; o >>= 1) sum += __shfl_xor_sync(0xffffffffu, sum, o);
  float inv = 1.0f / sum;
  g_p[row * MM + lane]      = e0 * inv;
  g_p[row * MM + lane + 32] = e1 * inv;
}

// ---------------------------------------------------------------------------
// Kernel 4: pass B — hv recurrence + output, per v-chunk.
// ---------------------------------------------------------------------------
__global__ __launch_bounds__(128) void passB_kernel(void) {
  int vch = blockIdx.x;
  int h = blockIdx.y, b = blockIdx.z;
  int tid = threadIdx.x;
  int v = tid & 31;
  int mg = tid >> 5;
  size_t row0 = (size_t)(b * HH + h) * TT;

  const float* vp = g_v + row0 * VDIM + vch * 32 + v;
  const float* pp = g_p + row0 * MM;
  const float* gp = g_ge + row0 * MM;
  float*       op = g_o + row0 * VDIM + vch * 32 + v;

  __shared__ float sp[MM];
  __shared__ float sge[MM];
  __shared__ float red[3][32];

  float hv[16];
  #pragma unroll
  for (int i = 0; i < 16; i++) hv[i] = 0.0f;

  float pg_n = (tid < 64) ? pp[tid] : gp[tid - 64];
  float vt_n = vp[0];

  for (int t = 0; t < TT; t++) {
    if (tid < 64) sp[tid] = pg_n; else sge[tid - 64] = pg_n;
    __syncthreads();
    float vt = vt_n;
    if (t + 1 < TT) {
      pg_n = (tid < 64) ? pp[(size_t)(t + 1) * MM + tid] : gp[(size_t)(t + 1) * MM + tid - 64];
      vt_n = vp[(size_t)(t + 1) * VDIM];
    }
    float4 o4 = make_float4(0.f, 0.f, 0.f, 0.f);
    #pragma unroll
    for (int i = 0; i < 4; i++) {
      float4 ge4 = *(float4*)&sge[mg * 16 + i * 4];
      float4 p4  = *(float4*)&sp[mg * 16 + i * 4];
      int bi = i * 4;
      hv[bi + 0] = (hv[bi + 0] - vt) * ge4.x + vt;  o4.x += p4.x * hv[bi + 0];
      hv[bi + 1] = (hv[bi + 1] - vt) * ge4.y + vt;  o4.y += p4.y * hv[bi + 1];
      hv[bi + 2] = (hv[bi + 2] - vt) * ge4.z + vt;  o4.z += p4.z * hv[bi + 2];
      hv[bi + 3] = (hv[bi + 3] - vt) * ge4.w + vt;  o4.w += p4.w * hv[bi + 3];
    }
    float osum = (o4.x + o4.y) + (o4.z + o4.w);
    if (mg) red[mg - 1][v] = osum;
    __syncthreads();
    if (mg == 0)
      op[(size_t)t * VDIM] = osum + red[0][v] + red[1][v] + red[2][v];
  }
}

// ---------------------------------------------------------------------------
// Kernel 5: per-head RMSNorm + layout change, tf32-rounded output.
// ---------------------------------------------------------------------------
__global__ __launch_bounds__(256) void norm_kernel(const float* __restrict__ gw) {
  int warp = threadIdx.x >> 5, lane = threadIdx.x & 31;
  size_t row = (size_t)blockIdx.x * 8 + warp;
  const float* orow = g_o + row * VDIM;
  float4 x0 = *(const float4*)(orow + lane * 8);
  float4 x1 = *(const float4*)(orow + lane * 8 + 4);
  float ss = x0.x * x0.x + x0.y * x0.y + x0.z * x0.z + x0.w * x0.w
           + x1.x * x1.x + x1.y * x1.y + x1.z * x1.z + x1.w * x1.w;
  #pragma unroll
  for (int o = 16; o > 0; o >>= 1) ss += __shfl_xor_sync(0xffffffffu, ss, o);
  float rstd = rsqrtf(ss * (1.0f / VDIM) + 1e-5f);
  int t = (int)(row & (TT - 1)); int bh = (int)(row >> 11); int b = bh >> 2, h = bh & 3;
  float* drow = g_on + ((size_t)(b * TT + t)) * DD + h * VDIM + lane * 8;
  float4 w0 = *(const float4*)(gw + lane * 8);
  float4 w1 = *(const float4*)(gw + lane * 8 + 4);
  float4 y0, y1;
  y0.x = cvt_rna_tf32(x0.x * rstd * w0.x); y0.y = cvt_rna_tf32(x0.y * rstd * w0.y);
  y0.z = cvt_rna_tf32(x0.z * rstd * w0.z); y0.w = cvt_rna_tf32(x0.w * rstd * w0.w);
  y1.x = cvt_rna_tf32(x1.x * rstd * w1.x); y1.y = cvt_rna_tf32(x1.y * rstd * w1.y);
  y1.z = cvt_rna_tf32(x1.z * rstd * w1.z); y1.w = cvt_rna_tf32(x1.w * rstd * w1.w);
  *(float4*)(drow)     = y0;
  *(float4*)(drow + 4) = y1;
}

// ---------------------------------------------------------------------------
// Kernel 6: output GEMM (tf32 tensor cores). g_on(8192x1024) @ Wo -> d_out.
// ---------------------------------------------------------------------------
__global__ __launch_bounds__(256) void out_gemm_tc(float* __restrict__ C) {
  __shared__ __align__(16) float sA[2][128 * LDA_S];
  __shared__ __align__(16) float sB[2][16 * LDB_S];

  int tid = threadIdx.x;
  int lane = tid & 31, warp = tid >> 5;
  int grp = lane >> 2, kq = lane & 3;
  int wm0 = (warp >> 2) * 64, wn0 = (warp & 3) * 32;
  int ncol0 = blockIdx.x * 128;

  const float* Ag = g_on + (size_t)(blockIdx.y * 128) * DD;
  const float* Bg = g_wo32 + ncol0;

  float acc[4][4][4];
  #pragma unroll
  for (int i = 0; i < 4; i++)
    #pragma unroll
    for (int j = 0; j < 4; j++)
      #pragma unroll
      for (int r = 0; r < 4; r++) acc[i][j][r] = 0.0f;

  gemm_load_stage(sA[0], sB[0], Ag, Bg, DD, 0, tid);
  cp_commit();

  for (int s = 0; s < 64; s++) {
    if (s < 63) {
      gemm_load_stage(sA[(s + 1) & 1], sB[(s + 1) & 1], Ag, Bg, DD, (s + 1) * 16, tid);
      cp_commit();
      cp_wait1();
    } else {
      cp_wait0();
    }
    __syncthreads();
    gemm_compute16(sA[s & 1], sB[s & 1], acc, grp, kq, wm0, wn0);
    __syncthreads();
  }

  #pragma unroll
  for (int mi = 0; mi < 4; mi++) {
    #pragma unroll
    for (int rh = 0; rh < 2; rh++) {
      size_t gm = (size_t)blockIdx.y * 128 + wm0 + 16 * mi + grp + 8 * rh;
      #pragma unroll
      for (int ni = 0; ni < 4; ni++) {
        float2 val;
        val.x = acc[mi][ni][rh * 2 + 0];
        val.y = acc[mi][ni][rh * 2 + 1];
        *(float2*)(C + gm * DD + ncol0 + wn0 + 8 * ni + 2 * kq) = val;
      }
    }
  }
}

// ---------------------------------------------------------------------------
extern "C" void kernel_launch(void* const* d_in, const int* in_sizes, int n_in,
                              void* d_out, int out_size) {
  const float* x  = (const float*)d_in[0];
  const float* Wq = (const float*)d_in[1];
  const float* Wk = (const float*)d_in[2];
  const float* Wv = (const float*)d_in[3];
  const float* Wf = (const float*)d_in[4];
  const float* gw = (const float*)d_in[5];
  const float* Wo = (const float*)d_in[6];
  float* out = (float*)d_out;

  float* xp;  cudaGetSymbolAddress((void**)&xp,  g_x32);
  float* wqp; cudaGetSymbolAddress((void**)&wqp, g_wq32);
  float* wkp; cudaGetSymbolAddress((void**)&wkp, g_wk32);
  float* wvp; cudaGetSymbolAddress((void**)&wvp, g_wv32);
  float* wfp; cudaGetSymbolAddress((void**)&wfp, g_wf32);
  float* wop; cudaGetSymbolAddress((void**)&wop, g_wo32);

  cvt_tf32_kernel<<<(BT * DD / 4 + 255) / 256, 256>>>(x, xp, BT * DD / 4);
  cvt_tf32_kernel<<<(DD * NQK / 4 + 255) / 256, 256>>>(Wq, wqp, DD * NQK / 4);
  cvt_tf32_kernel<<<(DD * NQK / 4 + 255) / 256, 256>>>(Wk, wkp, DD * NQK / 4);
  cvt_tf32_kernel<<<(DD * NQK / 4 + 255) / 256, 256>>>(Wv, wvp, DD * NQK / 4);
  cvt_tf32_kernel<<<(DD * HH * MM / 4 + 255) / 256, 256>>>(Wf, wfp, DD * HH * MM / 4);
  cvt_tf32_kernel<<<(DD * DD / 4 + 255) / 256, 256>>>(Wo, wop, DD * DD / 4);

  proj_gemm_tc<<<dim3(26, 64), 256>>>();
  passA_kernel<<<dim3(KCH, HH, BB), 64>>>();
  softmax_kernel<<<4096, 256>>>();
  passB_kernel<<<dim3(VCH, HH, BB), 128>>>();
  norm_kernel<<<4096, 256>>>(gw);
  out_gemm_tc<<<dim3(8, 64), 256>>>(out);
}

// round 4
// speedup vs baseline: 1.3404x; 1.0015x over previous
#include <cuda_runtime.h>
#include <math.h>
#include <stdint.h>

// Problem constants
#define BB 4
#define TT 2048
#define DD 1024
#define HH 4
#define KDIM 256
#define VDIM 256
#define MM 64
#define BT (BB*TT)            // 8192
#define NQK (HH*KDIM)         // 1024
#define KCH 16                // k-chunks in pass A (16 k each)
#define VCH 8                 // v-chunks in pass B (32 v each)

#define LDA_S 20              // smem A row stride (floats), tile 128 x 16
#define LDB_S 136             // smem B row stride (floats), tile 16 x 128

// Scratch (static device allocations; no cudaMalloc allowed)
__device__ float g_x32[(size_t)BT*DD];          // tf32-rounded x
__device__ float g_wq32[DD*NQK];
__device__ float g_wk32[DD*NQK];
__device__ float g_wv32[DD*NQK];
__device__ float g_wf32[DD*HH*MM];
__device__ float g_wo32[DD*DD];
__device__ float g_q [BB*HH*TT*KDIM];           // swish(xWq)*scale, [b,h,t,k]
__device__ float g_k [BB*HH*TT*KDIM];           // swish(xWk),       [b,h,t,k]
__device__ float g_v [BB*HH*TT*VDIM];           // xWv,              [b,h,t,v]
__device__ float g_ge[BB*HH*TT*MM];             // exp(f),           [b,h,t,m]
__device__ float g_part[(size_t)BB*HH*TT*KCH*MM]; // partial logits
__device__ float g_p [BB*HH*TT*MM];             // softmax probs  [b,h,t,m]
__device__ float g_o [BB*HH*TT*VDIM];           // pre-norm output [b,h,t,v]
__device__ float g_on[(size_t)BT*DD];           // normalized (tf32-rounded)

// ---------------------------------------------------------------------------
// tf32 helpers
// ---------------------------------------------------------------------------
__device__ __forceinline__ float cvt_rna_tf32(float x) {
  uint32_t r;
  asm("cvt.rna.tf32.f32 %0, %1;" : "=r"(r) : "f"(x));   // tf32 dest is .b32
  return __uint_as_float(r);
}

__device__ __forceinline__ void mma_tf32(float* c, const uint32_t* a, const uint32_t* b) {
  asm volatile(
      "mma.sync.aligned.m16n8k8.row.col.f32.tf32.tf32.f32 "
      "{%0,%1,%2,%3}, {%4,%5,%6,%7}, {%8,%9}, {%0,%1,%2,%3};"
      : "+f"(c[0]), "+f"(c[1]), "+f"(c[2]), "+f"(c[3])
      : "r"(a[0]), "r"(a[1]), "r"(a[2]), "r"(a[3]), "r"(b[0]), "r"(b[1]));
}

__device__ __forceinline__ void cpa16(void* smem, const void* g) {
  uint32_t s = (uint32_t)__cvta_generic_to_shared(smem);
  asm volatile("cp.async.cg.shared.global [%0], [%1], 16;" :: "r"(s), "l"(g));
}
__device__ __forceinline__ void cp_commit() { asm volatile("cp.async.commit_group;"); }
__device__ __forceinline__ void cp_wait1() { asm volatile("cp.async.wait_group 1;"); }
__device__ __forceinline__ void cp_wait0() { asm volatile("cp.async.wait_group 0;"); }

// ---------------------------------------------------------------------------
// Kernel 0: round fp32 -> tf32 (rna) elementwise, float4-wide.
// ---------------------------------------------------------------------------
__global__ __launch_bounds__(256) void cvt_tf32_kernel(
    const float* __restrict__ src, float* __restrict__ dst, int n4) {
  int i = blockIdx.x * 256 + threadIdx.x;
  if (i < n4) {
    float4 v = ((const float4*)src)[i];
    v.x = cvt_rna_tf32(v.x); v.y = cvt_rna_tf32(v.y);
    v.z = cvt_rna_tf32(v.z); v.w = cvt_rna_tf32(v.w);
    ((float4*)dst)[i] = v;
  }
}

// ---------------------------------------------------------------------------
// Shared GEMM machinery: CTA 128x128, 8 warps (2x4), warp 64x32, k-slab 16.
// ---------------------------------------------------------------------------
__device__ __forceinline__ void gemm_load_stage(
    float* sA, float* sB, const float* Ag, const float* Bg, int ldb, int k0, int tid) {
  int ac = tid * 2;
  {
    int r = ac >> 2, s = (ac & 3) * 4;
    cpa16(&sA[r * LDA_S + s], Ag + (size_t)r * DD + k0 + s);
  }
  {
    int r = (ac + 1) >> 2, s = ((ac + 1) & 3) * 4;
    cpa16(&sA[r * LDA_S + s], Ag + (size_t)r * DD + k0 + s);
  }
  int bc = tid * 2;
  {
    int r = bc >> 5, s = (bc & 31) * 4;
    cpa16(&sB[r * LDB_S + s], Bg + (size_t)(k0 + r) * ldb + s);
  }
  {
    int r = (bc + 1) >> 5, s = ((bc + 1) & 31) * 4;
    cpa16(&sB[r * LDB_S + s], Bg + (size_t)(k0 + r) * ldb + s);
  }
}

__device__ __forceinline__ void gemm_compute16(
    const float* sA, const float* sB, float acc[4][4][4],
    int grp, int kq, int wm0, int wn0) {
  #pragma unroll
  for (int kb = 0; kb < 16; kb += 8) {
    uint32_t a[4][4], b[4][2];
    #pragma unroll
    for (int mi = 0; mi < 4; mi++) {
      const uint32_t* ap = (const uint32_t*)(sA + (wm0 + 16 * mi + grp) * LDA_S + kb + kq);
      a[mi][0] = ap[0];
      a[mi][1] = ap[8 * LDA_S];
      a[mi][2] = ap[4];
      a[mi][3] = ap[8 * LDA_S + 4];
    }
    #pragma unroll
    for (int ni = 0; ni < 4; ni++) {
      const uint32_t* bp = (const uint32_t*)(sB + (kb + kq) * LDB_S + wn0 + 8 * ni + grp);
      b[ni][0] = bp[0];
      b[ni][1] = bp[4 * LDB_S];
    }
    #pragma unroll
    for (int mi = 0; mi < 4; mi++)
      #pragma unroll
      for (int ni = 0; ni < 4; ni++)
        mma_tf32(acc[mi][ni], a[mi], b[ni]);
  }
}

// ---------------------------------------------------------------------------
// Kernel 1: fused projection GEMM (tf32 tensor cores) + activation epilogue.
// ---------------------------------------------------------------------------
__global__ __launch_bounds__(256) void proj_gemm_tc(void) {
  __shared__ __align__(16) float sA[2][128 * LDA_S];
  __shared__ __align__(16) float sB[2][16 * LDB_S];

  int nt = blockIdx.x;
  const float* Wb; int ldb, seg, ncol0;
  if (nt < 8)       { Wb = g_wq32; ldb = NQK;   seg = 0; ncol0 = nt       * 128; }
  else if (nt < 16) { Wb = g_wk32; ldb = NQK;   seg = 1; ncol0 = (nt - 8) * 128; }
  else if (nt < 24) { Wb = g_wv32; ldb = NQK;   seg = 2; ncol0 = (nt - 16) * 128; }
  else              { Wb = g_wf32; ldb = HH*MM; seg = 3; ncol0 = (nt - 24) * 128; }

  int tid = threadIdx.x;
  int lane = tid & 31, warp = tid >> 5;
  int grp = lane >> 2, kq = lane & 3;
  int wm0 = (warp >> 2) * 64, wn0 = (warp & 3) * 32;

  const float* Ag = g_x32 + (size_t)(blockIdx.y * 128) * DD;
  const float* Bg = Wb + ncol0;

  float acc[4][4][4];
  #pragma unroll
  for (int i = 0; i < 4; i++)
    #pragma unroll
    for (int j = 0; j < 4; j++)
      #pragma unroll
      for (int r = 0; r < 4; r++) acc[i][j][r] = 0.0f;

  gemm_load_stage(sA[0], sB[0], Ag, Bg, ldb, 0, tid);
  cp_commit();

  for (int s = 0; s < 64; s++) {
    if (s < 63) {
      gemm_load_stage(sA[(s + 1) & 1], sB[(s + 1) & 1], Ag, Bg, ldb, (s + 1) * 16, tid);
      cp_commit();
      cp_wait1();
    } else {
      cp_wait0();
    }
    __syncthreads();
    gemm_compute16(sA[s & 1], sB[s & 1], acc, grp, kq, wm0, wn0);
    __syncthreads();
  }

  #pragma unroll
  for (int mi = 0; mi < 4; mi++) {
    #pragma unroll
    for (int rh = 0; rh < 2; rh++) {
      int gm = blockIdx.y * 128 + wm0 + 16 * mi + grp + 8 * rh;   // b*T + t
      int b = gm >> 11, t = gm & (TT - 1);
      #pragma unroll
      for (int ni = 0; ni < 4; ni++) {
        #pragma unroll
        for (int cc = 0; cc < 2; cc++) {
          float u = acc[mi][ni][rh * 2 + cc];
          int gn = ncol0 + wn0 + 8 * ni + 2 * kq + cc;
          if (seg <= 1) {
            float sw = u / (1.0f + expf(-u));          // swish
            if (seg == 0) sw *= 0.0625f;               // fold K^-0.5 into q
            int h = gn >> 8, c = gn & 255;
            float* dst = (seg == 0) ? g_q : g_k;
            dst[((size_t)((b * HH + h) * TT + t)) * KDIM + c] = sw;
          } else if (seg == 2) {
            int h = gn >> 8, c = gn & 255;
            g_v[((size_t)((b * HH + h) * TT + t)) * VDIM + c] = u;
          } else {
            float ls = fminf(u, 0.0f) - log1pf(expf(-fabsf(u)));
            float ge = expf(0.125f * ls);
            int h = gn >> 6, c = gn & 63;
            g_ge[((size_t)((b * HH + h) * TT + t)) * MM + c] = ge;
          }
        }
      }
    }
  }
}

// ---------------------------------------------------------------------------
// Kernel 2: pass A — hk recurrence + partial logits per k-chunk (16 k/CTA).
// ---------------------------------------------------------------------------
__global__ __launch_bounds__(64) void passA_kernel(void) {
  int chunk = blockIdx.x;
  int h = blockIdx.y, b = blockIdx.z;
  int m = threadIdx.x;
  size_t row0 = (size_t)(b * HH + h) * TT;

  const float* kp  = g_k  + row0 * KDIM + chunk * 16;
  const float* qp  = g_q  + row0 * KDIM + chunk * 16;
  const float* gep = g_ge + row0 * MM + m;
  float*       pp  = g_part + ((size_t)row0 * KCH + chunk) * MM + m;

  __shared__ float4 skq[8];

  float4 hk[4];
  #pragma unroll
  for (int i = 0; i < 4; i++) hk[i] = make_float4(0.f, 0.f, 0.f, 0.f);

  float kq_n = 0.0f;
  if (m < 16) kq_n = kp[m];
  else if (m < 32) kq_n = qp[m - 16];
  float ge_n = gep[0];

  for (int t = 0; t < TT; t++) {
    if (m < 32) ((float*)skq)[m] = kq_n;
    __syncthreads();
    float ge = ge_n;
    float s = 1.0f - ge;
    if (t + 1 < TT) {
      if (m < 16)      kq_n = kp[(size_t)(t + 1) * KDIM + m];
      else if (m < 32) kq_n = qp[(size_t)(t + 1) * KDIM + m - 16];
      ge_n = gep[(size_t)(t + 1) * MM];
    }
    float4 a0 = make_float4(0.f, 0.f, 0.f, 0.f);
    #pragma unroll
    for (int i = 0; i < 4; i++) {
      float4 kv = skq[i];
      float4 qv = skq[4 + i];
      hk[i].x = hk[i].x * ge + kv.x * s;  a0.x += qv.x * hk[i].x;
      hk[i].y = hk[i].y * ge + kv.y * s;  a0.y += qv.y * hk[i].y;
      hk[i].z = hk[i].z * ge + kv.z * s;  a0.z += qv.z * hk[i].z;
      hk[i].w = hk[i].w * ge + kv.w * s;  a0.w += qv.w * hk[i].w;
    }
    pp[(size_t)t * (KCH * MM)] = (a0.x + a0.y) + (a0.z + a0.w);
    __syncthreads();
  }
}

// ---------------------------------------------------------------------------
// Kernel 3: reduce partials + softmax over M=64. One warp per (b,h,t).
// ---------------------------------------------------------------------------
__global__ __launch_bounds__(256) void softmax_kernel(void) {
  int warp = threadIdx.x >> 5, lane = threadIdx.x & 31;
  size_t row = (size_t)blockIdx.x * 8 + warp;
  const float* pp = g_part + row * (KCH * MM);
  float l0 = 0.f, l1 = 0.f;
  #pragma unroll
  for (int c = 0; c < KCH; c++) {
    l0 += pp[c * MM + lane];
    l1 += pp[c * MM + lane + 32];
  }
  float mx = fmaxf(l0, l1);
  #pragma unroll
  for (int o = 16; o > 0; o >>= 1) mx = fmaxf(mx, __shfl_xor_sync(0xffffffffu, mx, o));
  float e0 = __expf(l0 - mx), e1 = __expf(l1 - mx);
  float sum = e0 + e1;
  #pragma unroll
  for (int o = 16; o > 0; o >>= 1) sum += __shfl_xor_sync(0xffffffffu, sum, o);
  float inv = 1.0f / sum;
  g_p[row * MM + lane]      = e0 * inv;
  g_p[row * MM + lane + 32] = e1 * inv;
}

// ---------------------------------------------------------------------------
// Kernel 4: pass B — hv recurrence + output, per v-chunk.
// ---------------------------------------------------------------------------
__global__ __launch_bounds__(128) void passB_kernel(void) {
  int vch = blockIdx.x;
  int h = blockIdx.y, b = blockIdx.z;
  int tid = threadIdx.x;
  int v = tid & 31;
  int mg = tid >> 5;
  size_t row0 = (size_t)(b * HH + h) * TT;

  const float* vp = g_v + row0 * VDIM + vch * 32 + v;
  const float* pp = g_p + row0 * MM;
  const float* gp = g_ge + row0 * MM;
  float*       op = g_o + row0 * VDIM + vch * 32 + v;

  __shared__ float sp[MM];
  __shared__ float sge[MM];
  __shared__ float red[3][32];

  float hv[16];
  #pragma unroll
  for (int i = 0; i < 16; i++) hv[i] = 0.0f;

  float pg_n = (tid < 64) ? pp[tid] : gp[tid - 64];
  float vt_n = vp[0];

  for (int t = 0; t < TT; t++) {
    if (tid < 64) sp[tid] = pg_n; else sge[tid - 64] = pg_n;
    __syncthreads();
    float vt = vt_n;
    if (t + 1 < TT) {
      pg_n = (tid < 64) ? pp[(size_t)(t + 1) * MM + tid] : gp[(size_t)(t + 1) * MM + tid - 64];
      vt_n = vp[(size_t)(t + 1) * VDIM];
    }
    float4 o4 = make_float4(0.f, 0.f, 0.f, 0.f);
    #pragma unroll
    for (int i = 0; i < 4; i++) {
      float4 ge4 = *(float4*)&sge[mg * 16 + i * 4];
      float4 p4  = *(float4*)&sp[mg * 16 + i * 4];
      int bi = i * 4;
      hv[bi + 0] = (hv[bi + 0] - vt) * ge4.x + vt;  o4.x += p4.x * hv[bi + 0];
      hv[bi + 1] = (hv[bi + 1] - vt) * ge4.y + vt;  o4.y += p4.y * hv[bi + 1];
      hv[bi + 2] = (hv[bi + 2] - vt) * ge4.z + vt;  o4.z += p4.z * hv[bi + 2];
      hv[bi + 3] = (hv[bi + 3] - vt) * ge4.w + vt;  o4.w += p4.w * hv[bi + 3];
    }
    float osum = (o4.x + o4.y) + (o4.z + o4.w);
    if (mg) red[mg - 1][v] = osum;
    __syncthreads();
    if (mg == 0)
      op[(size_t)t * VDIM] = osum + red[0][v] + red[1][v] + red[2][v];
  }
}

// ---------------------------------------------------------------------------
// Kernel 5: per-head RMSNorm + layout change, tf32-rounded output.
// ---------------------------------------------------------------------------
__global__ __launch_bounds__(256) void norm_kernel(const float* __restrict__ gw) {
  int warp = threadIdx.x >> 5, lane = threadIdx.x & 31;
  size_t row = (size_t)blockIdx.x * 8 + warp;
  const float* orow = g_o + row * VDIM;
  float4 x0 = *(const float4*)(orow + lane * 8);
  float4 x1 = *(const float4*)(orow + lane * 8 + 4);
  float ss = x0.x * x0.x + x0.y * x0.y + x0.z * x0.z + x0.w * x0.w
           + x1.x * x1.x + x1.y * x1.y + x1.z * x1.z + x1.w * x1.w;
  #pragma unroll
  for (int o = 16; o > 0; o >>= 1) ss += __shfl_xor_sync(0xffffffffu, ss, o);
  float rstd = rsqrtf(ss * (1.0f / VDIM) + 1e-5f);
  int t = (int)(row & (TT - 1)); int bh = (int)(row >> 11); int b = bh >> 2, h = bh & 3;
  float* drow = g_on + ((size_t)(b * TT + t)) * DD + h * VDIM + lane * 8;
  float4 w0 = *(const float4*)(gw + lane * 8);
  float4 w1 = *(const float4*)(gw + lane * 8 + 4);
  float4 y0, y1;
  y0.x = cvt_rna_tf32(x0.x * rstd * w0.x); y0.y = cvt_rna_tf32(x0.y * rstd * w0.y);
  y0.z = cvt_rna_tf32(x0.z * rstd * w0.z); y0.w = cvt_rna_tf32(x0.w * rstd * w0.w);
  y1.x = cvt_rna_tf32(x1.x * rstd * w1.x); y1.y = cvt_rna_tf32(x1.y * rstd * w1.y);
  y1.z = cvt_rna_tf32(x1.z * rstd * w1.z); y1.w = cvt_rna_tf32(x1.w * rstd * w1.w);
  *(float4*)(drow)     = y0;
  *(float4*)(drow + 4) = y1;
}

// ---------------------------------------------------------------------------
// Kernel 6: output GEMM (tf32 tensor cores). g_on(8192x1024) @ Wo -> d_out.
// ---------------------------------------------------------------------------
__global__ __launch_bounds__(256) void out_gemm_tc(float* __restrict__ C) {
  __shared__ __align__(16) float sA[2][128 * LDA_S];
  __shared__ __align__(16) float sB[2][16 * LDB_S];

  int tid = threadIdx.x;
  int lane = tid & 31, warp = tid >> 5;
  int grp = lane >> 2, kq = lane & 3;
  int wm0 = (warp >> 2) * 64, wn0 = (warp & 3) * 32;
  int ncol0 = blockIdx.x * 128;

  const float* Ag = g_on + (size_t)(blockIdx.y * 128) * DD;
  const float* Bg = g_wo32 + ncol0;

  float acc[4][4][4];
  #pragma unroll
  for (int i = 0; i < 4; i++)
    #pragma unroll
    for (int j = 0; j < 4; j++)
      #pragma unroll
      for (int r = 0; r < 4; r++) acc[i][j][r] = 0.0f;

  gemm_load_stage(sA[0], sB[0], Ag, Bg, DD, 0, tid);
  cp_commit();

  for (int s = 0; s < 64; s++) {
    if (s < 63) {
      gemm_load_stage(sA[(s + 1) & 1], sB[(s + 1) & 1], Ag, Bg, DD, (s + 1) * 16, tid);
      cp_commit();
      cp_wait1();
    } else {
      cp_wait0();
    }
    __syncthreads();
    gemm_compute16(sA[s & 1], sB[s & 1], acc, grp, kq, wm0, wn0);
    __syncthreads();
  }

  #pragma unroll
  for (int mi = 0; mi < 4; mi++) {
    #pragma unroll
    for (int rh = 0; rh < 2; rh++) {
      size_t gm = (size_t)blockIdx.y * 128 + wm0 + 16 * mi + grp + 8 * rh;
      #pragma unroll
      for (int ni = 0; ni < 4; ni++) {
        float2 val;
        val.x = acc[mi][ni][rh * 2 + 0];
        val.y = acc[mi][ni][rh * 2 + 1];
        *(float2*)(C + gm * DD + ncol0 + wn0 + 8 * ni + 2 * kq) = val;
      }
    }
  }
}

// ---------------------------------------------------------------------------
extern "C" void kernel_launch(void* const* d_in, const int* in_sizes, int n_in,
                              void* d_out, int out_size) {
  const float* x  = (const float*)d_in[0];
  const float* Wq = (const float*)d_in[1];
  const float* Wk = (const float*)d_in[2];
  const float* Wv = (const float*)d_in[3];
  const float* Wf = (const float*)d_in[4];
  const float* gw = (const float*)d_in[5];
  const float* Wo = (const float*)d_in[6];
  float* out = (float*)d_out;

  float* xp;  cudaGetSymbolAddress((void**)&xp,  g_x32);
  float* wqp; cudaGetSymbolAddress((void**)&wqp, g_wq32);
  float* wkp; cudaGetSymbolAddress((void**)&wkp, g_wk32);
  float* wvp; cudaGetSymbolAddress((void**)&wvp, g_wv32);
  float* wfp; cudaGetSymbolAddress((void**)&wfp, g_wf32);
  float* wop; cudaGetSymbolAddress((void**)&wop, g_wo32);

  cvt_tf32_kernel<<<(BT * DD / 4 + 255) / 256, 256>>>(x, xp, BT * DD / 4);
  cvt_tf32_kernel<<<(DD * NQK / 4 + 255) / 256, 256>>>(Wq, wqp, DD * NQK / 4);
  cvt_tf32_kernel<<<(DD * NQK / 4 + 255) / 256, 256>>>(Wk, wkp, DD * NQK / 4);
  cvt_tf32_kernel<<<(DD * NQK / 4 + 255) / 256, 256>>>(Wv, wvp, DD * NQK / 4);
  cvt_tf32_kernel<<<(DD * HH * MM / 4 + 255) / 256, 256>>>(Wf, wfp, DD * HH * MM / 4);
  cvt_tf32_kernel<<<(DD * DD / 4 + 255) / 256, 256>>>(Wo, wop, DD * DD / 4);

  proj_gemm_tc<<<dim3(26, 64), 256>>>();
  passA_kernel<<<dim3(KCH, HH, BB), 64>>>();
  softmax_kernel<<<4096, 256>>>();
  passB_kernel<<<dim3(VCH, HH, BB), 128>>>();
  norm_kernel<<<4096, 256>>>(gw);
  out_gemm_tc<<<dim3(8, 64), 256>>>(out);
}